// round 15
// baseline (speedup 1.0000x reference)
#include <cuda_runtime.h>
#include <cuda_fp16.h>
#include <cstdint>

// ---------------- problem dims ----------------
static constexpr int BB = 8192;   // batch
static constexpr int HD = 1024;   // hidden
static constexpr int KK = 2048;   // IN + H (concatenated K)
static constexpr int N4 = 4096;   // 4 gates * H (interleaved: n = o*4 + g)

// ---------------- GEMM tiling ----------------
static constexpr int BM = 128;
static constexpr int BN = 128;
static constexpr int BK = 64;          // 64 fp16 = 128 bytes per row (xor swizzle)
static constexpr int NK = KK / BK;     // 32
static constexpr int NT = 128;         // 4 warps: 2 along M x 2 along N, warp tile 64x64
static constexpr int NWARP = NT / 32;  // 4

static constexpr int A_BYTES = BM * 128;   // 16 KB per stage
static constexpr int B_BYTES = BN * 128;   // 16 KB per stage
static constexpr int STAGE_BYTES = A_BYTES + B_BYTES;     // 32 KB
static constexpr int OFF_MBAR  = 512;                     // 6 mbarriers (48B)
static constexpr int OFF_STAGE = 1024;                    // bias occupies [0,512)
static constexpr int SMEM_TOTAL = OFF_STAGE + 3 * STAGE_BYTES;   // 99328 -> 2 CTAs/SM

// ---------------- scratch (static device memory; no cudaMalloc allowed) ----------------
__device__ __half g_A[(size_t)BB * KK];   // [8192, 2048] fp16, row b = [x_b | h_b]
__device__ __half g_W[(size_t)N4 * KK];   // [4096, 2048] fp16, row n=o*4+g = [Wx[g,o,:] | Wh[g,o,:]]
__device__ float  g_bias[N4];             // bx + bh, gate-interleaved

// ---------------- PTX helpers ----------------
__device__ __forceinline__ uint32_t smem_u32(const void* p) {
    uint32_t a;
    asm("{ .reg .u64 t; cvta.to.shared.u64 t, %1; cvt.u32.u64 %0, t; }" : "=r"(a) : "l"(p));
    return a;
}
__device__ __forceinline__ void cpa16(uint32_t dst, const void* src) {
    asm volatile("cp.async.cg.shared.global [%0], [%1], 16;" :: "r"(dst), "l"(src) : "memory");
}
__device__ __forceinline__ void ldsm4(uint32_t* r, uint32_t addr) {
    asm volatile("ldmatrix.sync.aligned.m8n8.x4.shared.b16 {%0,%1,%2,%3}, [%4];"
                 : "=r"(r[0]), "=r"(r[1]), "=r"(r[2]), "=r"(r[3]) : "r"(addr));
}
__device__ __forceinline__ void mma16816(float* c, const uint32_t* a, const uint32_t* b) {
    asm volatile("mma.sync.aligned.m16n8k16.row.col.f32.f16.f16.f32 "
                 "{%0,%1,%2,%3}, {%4,%5,%6,%7}, {%8,%9}, {%0,%1,%2,%3};"
                 : "+f"(c[0]), "+f"(c[1]), "+f"(c[2]), "+f"(c[3])
                 : "r"(a[0]), "r"(a[1]), "r"(a[2]), "r"(a[3]), "r"(b[0]), "r"(b[1]));
}

// mbarrier primitives (sm_80+/sm_90 base features; NOT 'a'-gated)
__device__ __forceinline__ void mbar_init(uint32_t a, uint32_t cnt) {
    asm volatile("mbarrier.init.shared.b64 [%0], %1;" :: "r"(a), "r"(cnt) : "memory");
}
__device__ __forceinline__ void mbar_arrive(uint32_t a) {
    asm volatile("mbarrier.arrive.shared.b64 _, [%0];" :: "r"(a) : "memory");
}
__device__ __forceinline__ void cpa_arrive_noinc(uint32_t a) {
    asm volatile("cp.async.mbarrier.arrive.noinc.shared.b64 [%0];" :: "r"(a) : "memory");
}
__device__ __forceinline__ void mbar_wait(uint32_t a, uint32_t parity) {
    uint32_t done;
    asm volatile("{\n\t.reg .pred p;\n\t"
                 "mbarrier.try_wait.parity.acquire.cta.shared::cta.b64 p, [%1], %2;\n\t"
                 "selp.b32 %0, 1, 0, p;\n\t}"
                 : "=r"(done) : "r"(a), "r"(parity) : "memory");
    while (!done) {
        asm volatile("{\n\t.reg .pred p;\n\t"
                     "mbarrier.try_wait.parity.acquire.cta.shared::cta.b64 p, [%1], %2, 0x989680;\n\t"
                     "selp.b32 %0, 1, 0, p;\n\t}"
                     : "=r"(done) : "r"(a), "r"(parity) : "memory");
    }
}

// fast activations via MUFU (ex2/rcp approx: error ~1e-6, negligible vs fp16 GEMM error)
__device__ __forceinline__ float fex2(float x) { float y; asm("ex2.approx.f32 %0, %1;" : "=f"(y) : "f"(x)); return y; }
__device__ __forceinline__ float frcp(float x) { float y; asm("rcp.approx.f32 %0, %1;" : "=f"(y) : "f"(x)); return y; }
__device__ __forceinline__ float sigf(float x)  { return frcp(1.0f + fex2(-1.4426950408889634f * x)); }
__device__ __forceinline__ float tanhf_(float x){ return 1.0f - 2.0f * frcp(1.0f + fex2(2.8853900817779268f * x)); }

// ---------------- fused pack kernel (fp32 -> fp16, concat + gate interleave + bias) ----------------
static constexpr int PACK_A_BLOCKS = (BB * KK / 8) / 256;   // 8192
static constexpr int PACK_W_BLOCKS = (N4 * KK / 8) / 256;   // 4096
static constexpr int PACK_BIAS_BLOCKS = N4 / 256;           // 16
static constexpr int PACK_BLOCKS = PACK_A_BLOCKS + PACK_W_BLOCKS + PACK_BIAS_BLOCKS;

__global__ void pack_all_kernel(const float* __restrict__ x, const float* __restrict__ h,
                                const float* __restrict__ Wx, const float* __restrict__ Wh,
                                const float* __restrict__ bx, const float* __restrict__ bh) {
    const int bid = blockIdx.x;
    if (bid < PACK_A_BLOCKS) {
        int t = bid * 256 + threadIdx.x;
        int row = t >> 8;
        int col = (t & 255) << 3;
        const float* src = (col < HD) ? (x + (size_t)row * HD + col)
                                      : (h + (size_t)row * HD + (col - HD));
        float4 f0 = ((const float4*)src)[0];
        float4 f1 = ((const float4*)src)[1];
        __half2 o[4];
        o[0] = __floats2half2_rn(f0.x, f0.y); o[1] = __floats2half2_rn(f0.z, f0.w);
        o[2] = __floats2half2_rn(f1.x, f1.y); o[3] = __floats2half2_rn(f1.z, f1.w);
        *(uint4*)(g_A + (size_t)row * KK + col) = *(const uint4*)o;
    } else if (bid < PACK_A_BLOCKS + PACK_W_BLOCKS) {
        int t = (bid - PACK_A_BLOCKS) * 256 + threadIdx.x;
        int n = t >> 8;                                    // n = o*4 + g (gate-interleaved)
        int col = (t & 255) << 3;
        int g = n & 3, o = n >> 2;
        const float* src = (col < HD) ? (Wx + ((size_t)g * HD + o) * HD + col)
                                      : (Wh + ((size_t)g * HD + o) * HD + (col - HD));
        float4 f0 = ((const float4*)src)[0];
        float4 f1 = ((const float4*)src)[1];
        __half2 q[4];
        q[0] = __floats2half2_rn(f0.x, f0.y); q[1] = __floats2half2_rn(f0.z, f0.w);
        q[2] = __floats2half2_rn(f1.x, f1.y); q[3] = __floats2half2_rn(f1.z, f1.w);
        *(uint4*)(g_W + (size_t)n * KK + col) = *(const uint4*)q;
    } else {
        int n = (bid - PACK_A_BLOCKS - PACK_W_BLOCKS) * 256 + threadIdx.x;
        int g = n & 3, o = n >> 2;
        g_bias[n] = bx[g * HD + o] + bh[g * HD + o];
    }
}

// ---------------- fused GEMM (HMMA mma.sync) + LSTM epilogue ----------------
// 2 CTAs per SM, 4 warps each (warp tile 64x64 -> bytes/MAC 0.0625: SMEM
// crossbar demand 1750cyc < 2048cyc tensor floor, no longer co-limiting).
// 255-reg budget (128 thr x 2 CTA) gives ptxas pipelining headroom.
// mbarrier full/empty rings; loader split into two 8-op bursts at ks bounds.
__global__ void __launch_bounds__(NT, 2)
lstm_gemm_kernel(const float* __restrict__ c_in, float* __restrict__ out) {
    extern __shared__ char smem[];
    const uint32_t sb  = smem_u32(smem);
    const int tid  = threadIdx.x;
    const int wid  = tid >> 5;
    const int lane = tid & 31;
    const int m0 = blockIdx.y * BM;
    const int n0 = blockIdx.x * BN;
    const int wm = wid & 1;        // 2 warps along M (64 rows each)
    const int wn = wid >> 1;       // 2 warps along N (64 cols each)

    // bias tile -> smem[0..512)
    ((float*)smem)[tid] = g_bias[n0 + tid];        // NT==BN==128

    // mbarriers: full[b] at 512+8b (count NT), empty[b] at 536+8b (count NWARP)
    const uint32_t F0 = sb + OFF_MBAR,      F1 = F0 + 8,  F2 = F0 + 16;
    const uint32_t E0 = sb + OFF_MBAR + 24, E1 = E0 + 8,  E2 = E0 + 16;
    if (tid == 0) {
        mbar_init(F0, NT);    mbar_init(F1, NT);    mbar_init(F2, NT);
        mbar_init(E0, NWARP); mbar_init(E1, NWARP); mbar_init(E2, NWARP);
    }
    __syncthreads();
    // pre-arrive (lane0 per warp): mark all buffers "empty" (completes empty phase 0)
    if (lane == 0) { mbar_arrive(E0); mbar_arrive(E1); mbar_arrive(E2); }

    // compile-time stage bases
    const uint32_t aS0 = sb + OFF_STAGE,       bS0 = aS0 + A_BYTES;
    const uint32_t aS1 = aS0 + STAGE_BYTES,    bS1 = aS1 + A_BYTES;
    const uint32_t aS2 = aS0 + 2*STAGE_BYTES,  bS2 = aS2 + A_BYTES;

    // ---- hoisted loader addressing (128 threads: 16 chunks each) ----
    // chunk idx = q*128+tid: cch = tid&7, r = q*16 + (tid>>3); r&7 constant.
    const int cch = tid & 7;
    const int rr  = tid >> 3;                       // 0..15
    const uint32_t dst_off = (uint32_t)rr * 128 + (uint32_t)((cch ^ (rr & 7)) << 4);
    const __half* pA = g_A + (size_t)(m0 + rr) * KK + cch * 8;
    const __half* pW = g_W + (size_t)(n0 + rr) * KK + cch * 8;
    const size_t QO = (size_t)16 * KK;              // 16 rows

    auto load_A = [&](uint32_t aDst) {
        #pragma unroll
        for (int q = 0; q < 8; q++)
            cpa16(aDst + dst_off + q * 2048, pA + (size_t)q * QO);
    };
    auto load_B = [&](uint32_t bDst) {              // also advances the cursors
        #pragma unroll
        for (int q = 0; q < 8; q++)
            cpa16(bDst + dst_off + q * 2048, pW + (size_t)q * QO);
        pA += BK; pW += BK;
    };

    // ---- ldmatrix addressing (factored swizzle: col(ks) = c0 ^ (2ks<<4)) ----
    const int a_row = wm * 64 + (lane & 15);
    const uint32_t a_rt = (uint32_t)a_row * 128;
    const uint32_t ac0 = (uint32_t)((((lane >> 4) ^ (a_row & 7))) << 4);
    const int b_row = wn * 64 + (lane & 7) + ((lane >> 4) << 3);
    const uint32_t b_rt = (uint32_t)b_row * 128;
    const uint32_t bc0 = (uint32_t)(((((lane >> 3) & 1) ^ (b_row & 7))) << 4);

    float acc[4][8][4];                          // mt(4 x 16 rows) x nt(8 x 8 cols) x frag
    #pragma unroll
    for (int mt = 0; mt < 4; mt++)
        #pragma unroll
        for (int nt = 0; nt < 8; nt++)
            #pragma unroll
            for (int v = 0; v < 4; v++) acc[mt][nt][v] = 0.0f;

    auto compute_ks = [&](uint32_t aBase, uint32_t bBase, int ks) {
        const uint32_t abase = aBase + a_rt;
        const uint32_t bbase = bBase + b_rt;
        uint32_t af[4][4], bf[4][4];
        const uint32_t ac = ac0 ^ (uint32_t)((2 * ks) << 4);
        const uint32_t bc = bc0 ^ (uint32_t)((2 * ks) << 4);
        #pragma unroll
        for (int np = 0; np < 4; np++)
            ldsm4(bf[np], bbase + np * 2048 + bc);
        #pragma unroll
        for (int mt = 0; mt < 4; mt++)
            ldsm4(af[mt], abase + mt * 2048 + ac);
        #pragma unroll
        for (int mt = 0; mt < 4; mt++)
            #pragma unroll
            for (int np = 0; np < 4; np++) {
                mma16816(acc[mt][2 * np],     af[mt], &bf[np][0]);
                mma16816(acc[mt][2 * np + 1], af[mt], &bf[np][2]);
            }
    };

    // one pipeline step: compute ks0..3 of C-buffer with the L-buffer loads split
    // into two 8-op bursts at ks boundaries (each covered by draining HMMAs).
    auto step = [&](uint32_t eL, uint32_t peL, uint32_t aL, uint32_t bL, uint32_t fL,
                    uint32_t fC, uint32_t pfC, uint32_t aC, uint32_t bC, uint32_t eC) {
        mbar_wait(fC, pfC);             // compute data ready (all threads' loads)
        compute_ks(aC, bC, 0);
        mbar_wait(eL, peL);             // buffer free (pre-satisfied in steady state)
        load_A(aL);
        compute_ks(aC, bC, 1);
        load_B(bL);
        cpa_arrive_noinc(fL);           // arrive when this thread's loads land
        compute_ks(aC, bC, 2);
        compute_ks(aC, bC, 3);
        if (lane == 0) mbar_arrive(eC); // warp done reading C-buffer
    };

    // prologue: 2 stages in flight (virgin buffers: no empty wait)
    load_A(aS0); load_B(bS0); cpa_arrive_noinc(F0);
    load_A(aS1); load_B(bS1); cpa_arrive_noinc(F1);

    // 30 iters: 5 rounds x 6 (parity period = lcm(3 stages, 2 phases)); all parities literal
    #pragma unroll 1
    for (int r = 0; r < 5; r++) {
        step(E2, 0, aS2, bS2, F2,  F0, 0, aS0, bS0, E0);   // u=0
        step(E0, 1, aS0, bS0, F0,  F1, 0, aS1, bS1, E1);   // u=1
        step(E1, 1, aS1, bS1, F1,  F2, 0, aS2, bS2, E2);   // u=2
        step(E2, 1, aS2, bS2, F2,  F0, 1, aS0, bS0, E0);   // u=3
        step(E0, 0, aS0, bS0, F0,  F1, 1, aS1, bS1, E1);   // u=4
        step(E1, 0, aS1, bS1, F1,  F2, 1, aS2, bS2, E2);   // u=5
    }
    // tail: iters 30,31 (no loads); full parities (it/3)&1 = 0
    mbar_wait(F0, 0);
    compute_ks(aS0, bS0, 0); compute_ks(aS0, bS0, 1);
    compute_ks(aS0, bS0, 2); compute_ks(aS0, bS0, 3);
    mbar_wait(F1, 0);
    compute_ks(aS1, bS1, 0); compute_ks(aS1, bS1, 1);
    compute_ks(aS1, bS1, 2); compute_ks(aS1, bS1, 3);

    // ---------------- epilogue: gate exchange via smem, fused LSTM ----------------
    __syncthreads();                            // all warps done before smem reuse
    float* gbuf = (float*)(smem + OFF_STAGE);   // 128 rows x 128 floats (xor-swizzled 8B slots)

    #pragma unroll
    for (int mt = 0; mt < 4; mt++) {
        #pragma unroll
        for (int nt = 0; nt < 8; nt++) {
            const int r0 = wm * 64 + mt * 16 + (lane >> 2);
            const int r1 = r0 + 8;
            const int sbase = wn * 32 + nt * 4 + (lane & 3);   // 8B slot index (64 per row)
            const uint32_t off0 = (uint32_t)r0 * 512 + (uint32_t)((sbase ^ ((r0 & 7) << 2)) << 3);
            const uint32_t off1 = (uint32_t)r1 * 512 + (uint32_t)((sbase ^ ((r1 & 7) << 2)) << 3);
            *(float2*)((char*)gbuf + off0) = make_float2(acc[mt][nt][0], acc[mt][nt][1]);
            *(float2*)((char*)gbuf + off1) = make_float2(acc[mt][nt][2], acc[mt][nt][3]);
        }
    }
    __syncthreads();

    {
        const int ocol = tid & 31;                 // output column within tile (32 outputs)
        const int rbase = tid >> 5;                // 4 row groups
        const float4 bias4 = *(const float4*)((const float*)smem + ocol * 4);
        const int obase = (n0 >> 2) + ocol;        // global output index
        #pragma unroll 4
        for (int i = 0; i < 32; i++) {
            const int r = rbase + 4 * i;
            const int b = m0 + r;
            const uint32_t off = (uint32_t)r * 512 +
                                 (uint32_t)(((2 * ocol) ^ ((r & 7) << 2)) << 3);
            float4 gt = *(const float4*)((const char*)gbuf + off);
            float gi = gt.x + bias4.x;
            float gf = gt.y + bias4.y;
            float gg = gt.z + bias4.z;
            float go = gt.w + bias4.w;
            float iv = sigf(gi), fv = sigf(gf), gv = tanhf_(gg), ov = sigf(go);
            float cold = c_in[(size_t)b * HD + obase];
            float cv = fv * cold + iv * gv;
            float hv = ov * tanhf_(cv);
            out[(size_t)b * HD + obase] = hv;
            out[(size_t)BB * HD + (size_t)b * HD + obase] = cv;
        }
    }
}

// ---------------- launch ----------------
extern "C" void kernel_launch(void* const* d_in, const int* in_sizes, int n_in,
                              void* d_out, int out_size) {
    const float* x  = (const float*)d_in[0];
    const float* h  = (const float*)d_in[1];
    const float* c  = (const float*)d_in[2];
    const float* Wx = (const float*)d_in[3];
    const float* bx = (const float*)d_in[4];
    const float* Wh = (const float*)d_in[5];
    const float* bh = (const float*)d_in[6];
    float* out = (float*)d_out;

    pack_all_kernel<<<PACK_BLOCKS, 256>>>(x, h, Wx, Wh, bx, bh);

    cudaFuncSetAttribute(lstm_gemm_kernel,
                         cudaFuncAttributeMaxDynamicSharedMemorySize, SMEM_TOTAL);
    dim3 grid(N4 / BN, BB / BM);   // (32, 64)
    lstm_gemm_kernel<<<grid, NT, SMEM_TOTAL>>>(c, out);
}

// round 16
// speedup vs baseline: 1.0271x; 1.0271x over previous
#include <cuda_runtime.h>
#include <cuda_fp16.h>
#include <cstdint>

// ---------------- problem dims ----------------
static constexpr int BB = 8192;   // batch
static constexpr int HD = 1024;   // hidden
static constexpr int KK = 2048;   // IN + H (concatenated K)
static constexpr int N4 = 4096;   // 4 gates * H (interleaved: n = o*4 + g)

// ---------------- GEMM tiling ----------------
static constexpr int BM = 128;
static constexpr int BN = 128;
static constexpr int BK = 64;          // 64 fp16 = 128 bytes per row (xor swizzle)
static constexpr int NK = KK / BK;     // 32
static constexpr int NT = 128;         // 4 warps: 2 along M x 2 along N, warp tile 64x64
static constexpr int NWARP = NT / 32;  // 4

static constexpr int A_BYTES = BM * 128;   // 16 KB per stage
static constexpr int B_BYTES = BN * 128;   // 16 KB per stage
static constexpr int STAGE_BYTES = A_BYTES + B_BYTES;     // 32 KB
static constexpr int OFF_MBAR  = 512;                     // 6 mbarriers (48B)
static constexpr int OFF_STAGE = 1024;                    // bias occupies [0,512)
static constexpr int SMEM_TOTAL = OFF_STAGE + 3 * STAGE_BYTES;   // 99328 -> 2 CTAs/SM

// ---------------- scratch (static device memory; no cudaMalloc allowed) ----------------
__device__ __half g_A[(size_t)BB * KK];   // [8192, 2048] fp16, row b = [x_b | h_b]
__device__ __half g_W[(size_t)N4 * KK];   // [4096, 2048] fp16, row n=o*4+g = [Wx[g,o,:] | Wh[g,o,:]]
__device__ float  g_bias[N4];             // bx + bh, gate-interleaved

// ---------------- PTX helpers ----------------
__device__ __forceinline__ uint32_t smem_u32(const void* p) {
    uint32_t a;
    asm("{ .reg .u64 t; cvta.to.shared.u64 t, %1; cvt.u32.u64 %0, t; }" : "=r"(a) : "l"(p));
    return a;
}
__device__ __forceinline__ void cpa16(uint32_t dst, const void* src) {
    asm volatile("cp.async.cg.shared.global [%0], [%1], 16;" :: "r"(dst), "l"(src) : "memory");
}
__device__ __forceinline__ void ldsm4(uint32_t* r, uint32_t addr) {
    asm volatile("ldmatrix.sync.aligned.m8n8.x4.shared.b16 {%0,%1,%2,%3}, [%4];"
                 : "=r"(r[0]), "=r"(r[1]), "=r"(r[2]), "=r"(r[3]) : "r"(addr));
}
__device__ __forceinline__ void mma16816(float* c, const uint32_t* a, const uint32_t* b) {
    asm volatile("mma.sync.aligned.m16n8k16.row.col.f32.f16.f16.f32 "
                 "{%0,%1,%2,%3}, {%4,%5,%6,%7}, {%8,%9}, {%0,%1,%2,%3};"
                 : "+f"(c[0]), "+f"(c[1]), "+f"(c[2]), "+f"(c[3])
                 : "r"(a[0]), "r"(a[1]), "r"(a[2]), "r"(a[3]), "r"(b[0]), "r"(b[1]));
}

// mbarrier primitives (sm_80+/sm_90 base features; NOT 'a'-gated)
__device__ __forceinline__ void mbar_init(uint32_t a, uint32_t cnt) {
    asm volatile("mbarrier.init.shared.b64 [%0], %1;" :: "r"(a), "r"(cnt) : "memory");
}
__device__ __forceinline__ void mbar_arrive(uint32_t a) {
    asm volatile("mbarrier.arrive.shared.b64 _, [%0];" :: "r"(a) : "memory");
}
__device__ __forceinline__ void cpa_arrive_noinc(uint32_t a) {
    asm volatile("cp.async.mbarrier.arrive.noinc.shared.b64 [%0];" :: "r"(a) : "memory");
}
__device__ __forceinline__ void mbar_wait(uint32_t a, uint32_t parity) {
    uint32_t done;
    asm volatile("{\n\t.reg .pred p;\n\t"
                 "mbarrier.try_wait.parity.acquire.cta.shared::cta.b64 p, [%1], %2;\n\t"
                 "selp.b32 %0, 1, 0, p;\n\t}"
                 : "=r"(done) : "r"(a), "r"(parity) : "memory");
    while (!done) {
        asm volatile("{\n\t.reg .pred p;\n\t"
                     "mbarrier.try_wait.parity.acquire.cta.shared::cta.b64 p, [%1], %2, 0x989680;\n\t"
                     "selp.b32 %0, 1, 0, p;\n\t}"
                     : "=r"(done) : "r"(a), "r"(parity) : "memory");
    }
}

// fast activations via MUFU (ex2/rcp approx: error ~1e-6, negligible vs fp16 GEMM error)
__device__ __forceinline__ float fex2(float x) { float y; asm("ex2.approx.f32 %0, %1;" : "=f"(y) : "f"(x)); return y; }
__device__ __forceinline__ float frcp(float x) { float y; asm("rcp.approx.f32 %0, %1;" : "=f"(y) : "f"(x)); return y; }
__device__ __forceinline__ float sigf(float x)  { return frcp(1.0f + fex2(-1.4426950408889634f * x)); }
__device__ __forceinline__ float tanhf_(float x){ return 1.0f - 2.0f * frcp(1.0f + fex2(2.8853900817779268f * x)); }

// ---------------- fused pack kernel (fp32 -> fp16, concat + gate interleave + bias) ----------------
static constexpr int PACK_A_BLOCKS = (BB * KK / 8) / 256;   // 8192
static constexpr int PACK_W_BLOCKS = (N4 * KK / 8) / 256;   // 4096
static constexpr int PACK_BIAS_BLOCKS = N4 / 256;           // 16
static constexpr int PACK_BLOCKS = PACK_A_BLOCKS + PACK_W_BLOCKS + PACK_BIAS_BLOCKS;

__global__ void pack_all_kernel(const float* __restrict__ x, const float* __restrict__ h,
                                const float* __restrict__ Wx, const float* __restrict__ Wh,
                                const float* __restrict__ bx, const float* __restrict__ bh) {
    const int bid = blockIdx.x;
    if (bid < PACK_A_BLOCKS) {
        int t = bid * 256 + threadIdx.x;
        int row = t >> 8;
        int col = (t & 255) << 3;
        const float* src = (col < HD) ? (x + (size_t)row * HD + col)
                                      : (h + (size_t)row * HD + (col - HD));
        float4 f0 = ((const float4*)src)[0];
        float4 f1 = ((const float4*)src)[1];
        __half2 o[4];
        o[0] = __floats2half2_rn(f0.x, f0.y); o[1] = __floats2half2_rn(f0.z, f0.w);
        o[2] = __floats2half2_rn(f1.x, f1.y); o[3] = __floats2half2_rn(f1.z, f1.w);
        *(uint4*)(g_A + (size_t)row * KK + col) = *(const uint4*)o;
    } else if (bid < PACK_A_BLOCKS + PACK_W_BLOCKS) {
        int t = (bid - PACK_A_BLOCKS) * 256 + threadIdx.x;
        int n = t >> 8;                                    // n = o*4 + g (gate-interleaved)
        int col = (t & 255) << 3;
        int g = n & 3, o = n >> 2;
        const float* src = (col < HD) ? (Wx + ((size_t)g * HD + o) * HD + col)
                                      : (Wh + ((size_t)g * HD + o) * HD + (col - HD));
        float4 f0 = ((const float4*)src)[0];
        float4 f1 = ((const float4*)src)[1];
        __half2 q[4];
        q[0] = __floats2half2_rn(f0.x, f0.y); q[1] = __floats2half2_rn(f0.z, f0.w);
        q[2] = __floats2half2_rn(f1.x, f1.y); q[3] = __floats2half2_rn(f1.z, f1.w);
        *(uint4*)(g_W + (size_t)n * KK + col) = *(const uint4*)q;
    } else {
        int n = (bid - PACK_A_BLOCKS - PACK_W_BLOCKS) * 256 + threadIdx.x;
        int g = n & 3, o = n >> 2;
        g_bias[n] = bx[g * HD + o] + bh[g * HD + o];
    }
}

// ---------------- fused GEMM (HMMA mma.sync) + LSTM epilogue ----------------
// 2 CTAs per SM, 4 warps each (warp tile 64x64: crossbar demand 1750cyc <
// 2048cyc tensor floor). FULL fragment double-buffer (regs ~230 of 255 budget)
// self-hides ldsm latency at 2 warps/SMSP: ks+1's ldsm issue before ks's HMMAs.
__global__ void __launch_bounds__(NT, 2)
lstm_gemm_kernel(const float* __restrict__ c_in, float* __restrict__ out) {
    extern __shared__ char smem[];
    const uint32_t sb  = smem_u32(smem);
    const int tid  = threadIdx.x;
    const int wid  = tid >> 5;
    const int lane = tid & 31;
    const int m0 = blockIdx.y * BM;
    const int n0 = blockIdx.x * BN;
    const int wm = wid & 1;        // 2 warps along M (64 rows each)
    const int wn = wid >> 1;       // 2 warps along N (64 cols each)

    // bias tile -> smem[0..512)
    ((float*)smem)[tid] = g_bias[n0 + tid];        // NT==BN==128

    // mbarriers: full[b] at 512+8b (count NT), empty[b] at 536+8b (count NWARP)
    const uint32_t F0 = sb + OFF_MBAR,      F1 = F0 + 8,  F2 = F0 + 16;
    const uint32_t E0 = sb + OFF_MBAR + 24, E1 = E0 + 8,  E2 = E0 + 16;
    if (tid == 0) {
        mbar_init(F0, NT);    mbar_init(F1, NT);    mbar_init(F2, NT);
        mbar_init(E0, NWARP); mbar_init(E1, NWARP); mbar_init(E2, NWARP);
    }
    __syncthreads();
    // pre-arrive (lane0 per warp): mark all buffers "empty" (completes empty phase 0)
    if (lane == 0) { mbar_arrive(E0); mbar_arrive(E1); mbar_arrive(E2); }

    // compile-time stage bases
    const uint32_t aS0 = sb + OFF_STAGE,       bS0 = aS0 + A_BYTES;
    const uint32_t aS1 = aS0 + STAGE_BYTES,    bS1 = aS1 + A_BYTES;
    const uint32_t aS2 = aS0 + 2*STAGE_BYTES,  bS2 = aS2 + A_BYTES;

    // ---- hoisted loader addressing (128 threads: 16 chunks each) ----
    const int cch = tid & 7;
    const int rr  = tid >> 3;                       // 0..15
    const uint32_t dst_off = (uint32_t)rr * 128 + (uint32_t)((cch ^ (rr & 7)) << 4);
    const __half* pA = g_A + (size_t)(m0 + rr) * KK + cch * 8;
    const __half* pW = g_W + (size_t)(n0 + rr) * KK + cch * 8;
    const size_t QO = (size_t)16 * KK;              // 16 rows

    auto load_A = [&](uint32_t aDst) {
        #pragma unroll
        for (int q = 0; q < 8; q++)
            cpa16(aDst + dst_off + q * 2048, pA + (size_t)q * QO);
    };
    auto load_B = [&](uint32_t bDst) {              // also advances the cursors
        #pragma unroll
        for (int q = 0; q < 8; q++)
            cpa16(bDst + dst_off + q * 2048, pW + (size_t)q * QO);
        pA += BK; pW += BK;
    };

    // ---- ldmatrix addressing (factored swizzle: col(ks) = c0 ^ (2ks<<4)) ----
    const int a_row = wm * 64 + (lane & 15);
    const uint32_t a_rt = (uint32_t)a_row * 128;
    const uint32_t ac0 = (uint32_t)((((lane >> 4) ^ (a_row & 7))) << 4);
    const int b_row = wn * 64 + (lane & 7) + ((lane >> 4) << 3);
    const uint32_t b_rt = (uint32_t)b_row * 128;
    const uint32_t bc0 = (uint32_t)(((((lane >> 3) & 1) ^ (b_row & 7))) << 4);

    float acc[4][8][4];                          // mt(4 x 16 rows) x nt(8 x 8 cols) x frag
    #pragma unroll
    for (int mt = 0; mt < 4; mt++)
        #pragma unroll
        for (int nt = 0; nt < 8; nt++)
            #pragma unroll
            for (int v = 0; v < 4; v++) acc[mt][nt][v] = 0.0f;

    // double-buffered fragments: ks even -> buf0, ks odd -> buf1
    uint32_t af[2][4][4], bf[2][4][4];

    auto ld_frags = [&](uint32_t abase, uint32_t bbase, int ks, int buf) {
        const uint32_t ac = ac0 ^ (uint32_t)((2 * ks) << 4);
        const uint32_t bc = bc0 ^ (uint32_t)((2 * ks) << 4);
        #pragma unroll
        for (int np = 0; np < 4; np++)
            ldsm4(bf[buf][np], bbase + np * 2048 + bc);
        #pragma unroll
        for (int mt = 0; mt < 4; mt++)
            ldsm4(af[buf][mt], abase + mt * 2048 + ac);
    };
    auto mma_buf = [&](int buf) {
        #pragma unroll
        for (int mt = 0; mt < 4; mt++)
            #pragma unroll
            for (int np = 0; np < 4; np++) {
                mma16816(acc[mt][2 * np],     af[buf][mt], &bf[buf][np][0]);
                mma16816(acc[mt][2 * np + 1], af[buf][mt], &bf[buf][np][2]);
            }
    };

    // one pipeline step: fragment-pipelined ks0..3 of C-buffer; L-buffer cp.async
    // bursts slipped between mma blocks; ks+1 ldsm issued before ks's HMMAs.
    auto step = [&](uint32_t eL, uint32_t peL, uint32_t aL, uint32_t bL, uint32_t fL,
                    uint32_t fC, uint32_t pfC, uint32_t aC, uint32_t bC, uint32_t eC) {
        const uint32_t abase = aC + a_rt;
        const uint32_t bbase = bC + b_rt;
        mbar_wait(fC, pfC);             // compute data ready (all threads' loads)
        ld_frags(abase, bbase, 0, 0);
        ld_frags(abase, bbase, 1, 1);   // prefetch ks1
        mma_buf(0);                     // ks0
        mbar_wait(eL, peL);             // buffer free (pre-satisfied in steady state)
        load_A(aL);
        ld_frags(abase, bbase, 2, 0);   // prefetch ks2
        mma_buf(1);                     // ks1
        load_B(bL);
        cpa_arrive_noinc(fL);           // arrive when this thread's loads land
        ld_frags(abase, bbase, 3, 1);   // prefetch ks3
        mma_buf(0);                     // ks2
        mma_buf(1);                     // ks3
        if (lane == 0) mbar_arrive(eC); // warp done reading C-buffer
    };

    // tail compute (no loads)
    auto tail_stage = [&](uint32_t aC, uint32_t bC) {
        const uint32_t abase = aC + a_rt;
        const uint32_t bbase = bC + b_rt;
        ld_frags(abase, bbase, 0, 0);
        ld_frags(abase, bbase, 1, 1);
        mma_buf(0);
        ld_frags(abase, bbase, 2, 0);
        mma_buf(1);
        ld_frags(abase, bbase, 3, 1);
        mma_buf(0);
        mma_buf(1);
    };

    // prologue: 2 stages in flight (virgin buffers: no empty wait)
    load_A(aS0); load_B(bS0); cpa_arrive_noinc(F0);
    load_A(aS1); load_B(bS1); cpa_arrive_noinc(F1);

    // 30 iters: 5 rounds x 6 (parity period = lcm(3 stages, 2 phases)); all parities literal
    #pragma unroll 1
    for (int r = 0; r < 5; r++) {
        step(E2, 0, aS2, bS2, F2,  F0, 0, aS0, bS0, E0);   // u=0
        step(E0, 1, aS0, bS0, F0,  F1, 0, aS1, bS1, E1);   // u=1
        step(E1, 1, aS1, bS1, F1,  F2, 0, aS2, bS2, E2);   // u=2
        step(E2, 1, aS2, bS2, F2,  F0, 1, aS0, bS0, E0);   // u=3
        step(E0, 0, aS0, bS0, F0,  F1, 1, aS1, bS1, E1);   // u=4
        step(E1, 0, aS1, bS1, F1,  F2, 1, aS2, bS2, E2);   // u=5
    }
    // tail: iters 30,31 (no loads); full parities (it/3)&1 = 0
    mbar_wait(F0, 0); tail_stage(aS0, bS0);
    mbar_wait(F1, 0); tail_stage(aS1, bS1);

    // ---------------- epilogue: gate exchange via smem, fused LSTM ----------------
    __syncthreads();                            // all warps done before smem reuse
    float* gbuf = (float*)(smem + OFF_STAGE);   // 128 rows x 128 floats (xor-swizzled 8B slots)

    #pragma unroll
    for (int mt = 0; mt < 4; mt++) {
        #pragma unroll
        for (int nt = 0; nt < 8; nt++) {
            const int r0 = wm * 64 + mt * 16 + (lane >> 2);
            const int r1 = r0 + 8;
            const int sbase = wn * 32 + nt * 4 + (lane & 3);   // 8B slot index (64 per row)
            const uint32_t off0 = (uint32_t)r0 * 512 + (uint32_t)((sbase ^ ((r0 & 7) << 2)) << 3);
            const uint32_t off1 = (uint32_t)r1 * 512 + (uint32_t)((sbase ^ ((r1 & 7) << 2)) << 3);
            *(float2*)((char*)gbuf + off0) = make_float2(acc[mt][nt][0], acc[mt][nt][1]);
            *(float2*)((char*)gbuf + off1) = make_float2(acc[mt][nt][2], acc[mt][nt][3]);
        }
    }
    __syncthreads();

    {
        const int ocol = tid & 31;                 // output column within tile (32 outputs)
        const int rbase = tid >> 5;                // 4 row groups
        const float4 bias4 = *(const float4*)((const float*)smem + ocol * 4);
        const int obase = (n0 >> 2) + ocol;        // global output index
        #pragma unroll 4
        for (int i = 0; i < 32; i++) {
            const int r = rbase + 4 * i;
            const int b = m0 + r;
            const uint32_t off = (uint32_t)r * 512 +
                                 (uint32_t)(((2 * ocol) ^ ((r & 7) << 2)) << 3);
            float4 gt = *(const float4*)((const char*)gbuf + off);
            float gi = gt.x + bias4.x;
            float gf = gt.y + bias4.y;
            float gg = gt.z + bias4.z;
            float go = gt.w + bias4.w;
            float iv = sigf(gi), fv = sigf(gf), gv = tanhf_(gg), ov = sigf(go);
            float cold = c_in[(size_t)b * HD + obase];
            float cv = fv * cold + iv * gv;
            float hv = ov * tanhf_(cv);
            out[(size_t)b * HD + obase] = hv;
            out[(size_t)BB * HD + (size_t)b * HD + obase] = cv;
        }
    }
}

// ---------------- launch ----------------
extern "C" void kernel_launch(void* const* d_in, const int* in_sizes, int n_in,
                              void* d_out, int out_size) {
    const float* x  = (const float*)d_in[0];
    const float* h  = (const float*)d_in[1];
    const float* c  = (const float*)d_in[2];
    const float* Wx = (const float*)d_in[3];
    const float* bx = (const float*)d_in[4];
    const float* Wh = (const float*)d_in[5];
    const float* bh = (const float*)d_in[6];
    float* out = (float*)d_out;

    pack_all_kernel<<<PACK_BLOCKS, 256>>>(x, h, Wx, Wh, bx, bh);

    cudaFuncSetAttribute(lstm_gemm_kernel,
                         cudaFuncAttributeMaxDynamicSharedMemorySize, SMEM_TOTAL);
    dim3 grid(N4 / BN, BB / BM);   // (32, 64)
    lstm_gemm_kernel<<<grid, NT, SMEM_TOTAL>>>(c, out);
}

// round 17
// speedup vs baseline: 1.0469x; 1.0193x over previous
#include <cuda_runtime.h>
#include <cuda_fp16.h>
#include <cstdint>

// ---------------- problem dims ----------------
static constexpr int BB = 8192;   // batch
static constexpr int HD = 1024;   // hidden
static constexpr int KK = 2048;   // IN + H (concatenated K)
static constexpr int N4 = 4096;   // 4 gates * H (interleaved: n = o*4 + g)

// ---------------- GEMM tiling ----------------
static constexpr int BM = 128;
static constexpr int BN = 128;
static constexpr int BK = 64;          // 64 fp16 = 128 bytes per row (xor swizzle)
static constexpr int NK = KK / BK;     // 32
static constexpr int NT = 256;         // 8 warps: 2 along M x 4 along N, warp tile 64x32
static constexpr int NWARP = NT / 32;  // 8

static constexpr int A_BYTES = BM * 128;   // 16 KB per stage
static constexpr int B_BYTES = BN * 128;   // 16 KB per stage
static constexpr int STAGE_BYTES = A_BYTES + B_BYTES;     // 32 KB
static constexpr int OFF_MBAR  = 512;                     // 6 mbarriers (48B)
static constexpr int OFF_STAGE = 1024;                    // bias occupies [0,512)
static constexpr int SMEM_TOTAL = OFF_STAGE + 3 * STAGE_BYTES;   // 99328 -> 2 CTAs/SM

// ---------------- scratch (static device memory; no cudaMalloc allowed) ----------------
__device__ __half g_A[(size_t)BB * KK];   // [8192, 2048] fp16, row b = [x_b | h_b]
__device__ __half g_W[(size_t)N4 * KK];   // [4096, 2048] fp16, row n=o*4+g = [Wx[g,o,:] | Wh[g,o,:]]
__device__ float  g_bias[N4];             // bx + bh, gate-interleaved

// ---------------- PTX helpers ----------------
__device__ __forceinline__ uint32_t smem_u32(const void* p) {
    uint32_t a;
    asm("{ .reg .u64 t; cvta.to.shared.u64 t, %1; cvt.u32.u64 %0, t; }" : "=r"(a) : "l"(p));
    return a;
}
__device__ __forceinline__ void cpa16(uint32_t dst, const void* src) {
    asm volatile("cp.async.cg.shared.global [%0], [%1], 16;" :: "r"(dst), "l"(src) : "memory");
}
__device__ __forceinline__ void ldsm4(uint32_t* r, uint32_t addr) {
    asm volatile("ldmatrix.sync.aligned.m8n8.x4.shared.b16 {%0,%1,%2,%3}, [%4];"
                 : "=r"(r[0]), "=r"(r[1]), "=r"(r[2]), "=r"(r[3]) : "r"(addr));
}
__device__ __forceinline__ void mma16816(float* c, const uint32_t* a, const uint32_t* b) {
    asm volatile("mma.sync.aligned.m16n8k16.row.col.f32.f16.f16.f32 "
                 "{%0,%1,%2,%3}, {%4,%5,%6,%7}, {%8,%9}, {%0,%1,%2,%3};"
                 : "+f"(c[0]), "+f"(c[1]), "+f"(c[2]), "+f"(c[3])
                 : "r"(a[0]), "r"(a[1]), "r"(a[2]), "r"(a[3]), "r"(b[0]), "r"(b[1]));
}

// mbarrier primitives (sm_80+/sm_90 base features; NOT 'a'-gated)
__device__ __forceinline__ void mbar_init(uint32_t a, uint32_t cnt) {
    asm volatile("mbarrier.init.shared.b64 [%0], %1;" :: "r"(a), "r"(cnt) : "memory");
}
__device__ __forceinline__ void mbar_arrive(uint32_t a) {
    asm volatile("mbarrier.arrive.shared.b64 _, [%0];" :: "r"(a) : "memory");
}
__device__ __forceinline__ void cpa_arrive_noinc(uint32_t a) {
    asm volatile("cp.async.mbarrier.arrive.noinc.shared.b64 [%0];" :: "r"(a) : "memory");
}
__device__ __forceinline__ void mbar_wait(uint32_t a, uint32_t parity) {
    uint32_t done;
    asm volatile("{\n\t.reg .pred p;\n\t"
                 "mbarrier.try_wait.parity.acquire.cta.shared::cta.b64 p, [%1], %2;\n\t"
                 "selp.b32 %0, 1, 0, p;\n\t}"
                 : "=r"(done) : "r"(a), "r"(parity) : "memory");
    while (!done) {
        asm volatile("{\n\t.reg .pred p;\n\t"
                     "mbarrier.try_wait.parity.acquire.cta.shared::cta.b64 p, [%1], %2, 0x989680;\n\t"
                     "selp.b32 %0, 1, 0, p;\n\t}"
                     : "=r"(done) : "r"(a), "r"(parity) : "memory");
    }
}

// fast activations via MUFU (ex2/rcp approx: error ~1e-6, negligible vs fp16 GEMM error)
__device__ __forceinline__ float fex2(float x) { float y; asm("ex2.approx.f32 %0, %1;" : "=f"(y) : "f"(x)); return y; }
__device__ __forceinline__ float frcp(float x) { float y; asm("rcp.approx.f32 %0, %1;" : "=f"(y) : "f"(x)); return y; }
__device__ __forceinline__ float sigf(float x)  { return frcp(1.0f + fex2(-1.4426950408889634f * x)); }
__device__ __forceinline__ float tanhf_(float x){ return 1.0f - 2.0f * frcp(1.0f + fex2(2.8853900817779268f * x)); }

// ---------------- fused pack kernel (fp32 -> fp16, concat + gate interleave + bias) ----------------
// 512 threads x 16 floats/thread: 3080 blocks total (4x fewer than before),
// 64B loads + 32B stores per thread for better sector efficiency.
static constexpr int PT = 512;
static constexpr int PACK_A_BLOCKS = (BB * KK / 16) / PT;   // 2048
static constexpr int PACK_W_BLOCKS = (N4 * KK / 16) / PT;   // 1024
static constexpr int PACK_BIAS_BLOCKS = N4 / PT;            // 8
static constexpr int PACK_BLOCKS = PACK_A_BLOCKS + PACK_W_BLOCKS + PACK_BIAS_BLOCKS;

__device__ __forceinline__ void cvt16(const float* __restrict__ src, __half* __restrict__ dst) {
    float4 f0 = ((const float4*)src)[0];
    float4 f1 = ((const float4*)src)[1];
    float4 f2 = ((const float4*)src)[2];
    float4 f3 = ((const float4*)src)[3];
    __half2 o[8];
    o[0] = __floats2half2_rn(f0.x, f0.y); o[1] = __floats2half2_rn(f0.z, f0.w);
    o[2] = __floats2half2_rn(f1.x, f1.y); o[3] = __floats2half2_rn(f1.z, f1.w);
    o[4] = __floats2half2_rn(f2.x, f2.y); o[5] = __floats2half2_rn(f2.z, f2.w);
    o[6] = __floats2half2_rn(f3.x, f3.y); o[7] = __floats2half2_rn(f3.z, f3.w);
    ((uint4*)dst)[0] = ((const uint4*)o)[0];
    ((uint4*)dst)[1] = ((const uint4*)o)[1];
}

__global__ void pack_all_kernel(const float* __restrict__ x, const float* __restrict__ h,
                                const float* __restrict__ Wx, const float* __restrict__ Wh,
                                const float* __restrict__ bx, const float* __restrict__ bh) {
    const int bid = blockIdx.x;
    if (bid < PACK_A_BLOCKS) {
        int t = bid * PT + threadIdx.x;
        int row = t >> 7;                 // 128 chunks of 16 per row
        int col = (t & 127) << 4;
        const float* src = (col < HD) ? (x + (size_t)row * HD + col)
                                      : (h + (size_t)row * HD + (col - HD));
        cvt16(src, g_A + (size_t)row * KK + col);
    } else if (bid < PACK_A_BLOCKS + PACK_W_BLOCKS) {
        int t = (bid - PACK_A_BLOCKS) * PT + threadIdx.x;
        int n = t >> 7;                   // n = o*4 + g (gate-interleaved)
        int col = (t & 127) << 4;
        int g = n & 3, o = n >> 2;
        const float* src = (col < HD) ? (Wx + ((size_t)g * HD + o) * HD + col)
                                      : (Wh + ((size_t)g * HD + o) * HD + (col - HD));
        cvt16(src, g_W + (size_t)n * KK + col);
    } else {
        int n = (bid - PACK_A_BLOCKS - PACK_W_BLOCKS) * PT + threadIdx.x;
        int g = n & 3, o = n >> 2;
        g_bias[n] = bx[g * HD + o] + bh[g * HD + o];
    }
}

// ---------------- fused GEMM (HMMA mma.sync) + LSTM epilogue ----------------
// R13 config (best measured GEMM: 275.2us, tensor 82.2%): 2 CTAs/SM, 8 warps,
// warp tile 64x32; mbarrier full/empty rings (per-warp empty arrives); loader
// split into two 4-op bursts interleaved at ks boundaries.
__global__ void __launch_bounds__(NT, 2)
lstm_gemm_kernel(const float* __restrict__ c_in, float* __restrict__ out) {
    extern __shared__ char smem[];
    const uint32_t sb  = smem_u32(smem);
    const int tid  = threadIdx.x;
    const int wid  = tid >> 5;
    const int lane = tid & 31;
    const int m0 = blockIdx.y * BM;
    const int n0 = blockIdx.x * BN;
    const int wm = wid & 1;        // 2 warps along M (64 rows each)
    const int wn = wid >> 1;       // 4 warps along N (32 cols each)

    // bias tile -> smem[0..512)
    if (tid < BN) ((float*)smem)[tid] = g_bias[n0 + tid];

    // mbarriers: full[b] at 512+8b (count NT), empty[b] at 536+8b (count NWARP)
    const uint32_t F0 = sb + OFF_MBAR,      F1 = F0 + 8,  F2 = F0 + 16;
    const uint32_t E0 = sb + OFF_MBAR + 24, E1 = E0 + 8,  E2 = E0 + 16;
    if (tid == 0) {
        mbar_init(F0, NT);    mbar_init(F1, NT);    mbar_init(F2, NT);
        mbar_init(E0, NWARP); mbar_init(E1, NWARP); mbar_init(E2, NWARP);
    }
    __syncthreads();
    // pre-arrive (lane0 per warp): mark all buffers "empty" (completes empty phase 0)
    if (lane == 0) { mbar_arrive(E0); mbar_arrive(E1); mbar_arrive(E2); }

    // compile-time stage bases
    const uint32_t aS0 = sb + OFF_STAGE,       bS0 = aS0 + A_BYTES;
    const uint32_t aS1 = aS0 + STAGE_BYTES,    bS1 = aS1 + A_BYTES;
    const uint32_t aS2 = aS0 + 2*STAGE_BYTES,  bS2 = aS2 + A_BYTES;

    // ---- hoisted loader addressing ----
    const int cch = tid & 7;
    const int rr  = tid >> 3;                       // 0..31
    const uint32_t dst_off = (uint32_t)rr * 128 + (uint32_t)((cch ^ (rr & 7)) << 4);
    const __half* pA = g_A + (size_t)(m0 + rr) * KK + cch * 8;
    const __half* pW = g_W + (size_t)(n0 + rr) * KK + cch * 8;
    const size_t QO = (size_t)32 * KK;              // 32 rows

    auto load_A = [&](uint32_t aDst) {
        cpa16(aDst + dst_off,         pA);
        cpa16(aDst + dst_off + 4096,  pA + QO);
        cpa16(aDst + dst_off + 8192,  pA + 2*QO);
        cpa16(aDst + dst_off + 12288, pA + 3*QO);
    };
    auto load_B = [&](uint32_t bDst) {              // also advances the cursors
        cpa16(bDst + dst_off,         pW);
        cpa16(bDst + dst_off + 4096,  pW + QO);
        cpa16(bDst + dst_off + 8192,  pW + 2*QO);
        cpa16(bDst + dst_off + 12288, pW + 3*QO);
        pA += BK; pW += BK;
    };

    // ---- ldmatrix addressing (factored swizzle: col(ks) = c0 ^ (2ks<<4)) ----
    const int a_row = wm * 64 + (lane & 15);
    const uint32_t a_rt = (uint32_t)a_row * 128;
    const uint32_t ac0 = (uint32_t)((((lane >> 4) ^ (a_row & 7))) << 4);
    const int b_row = wn * 32 + (lane & 7) + ((lane >> 4) << 3);
    const uint32_t b_rt = (uint32_t)b_row * 128;
    const uint32_t bc0 = (uint32_t)(((((lane >> 3) & 1) ^ (b_row & 7))) << 4);

    float acc[4][4][4];                          // mt(4 x 16 rows) x nt(4 x 8 cols) x frag
    #pragma unroll
    for (int mt = 0; mt < 4; mt++)
        #pragma unroll
        for (int nt = 0; nt < 4; nt++)
            #pragma unroll
            for (int v = 0; v < 4; v++) acc[mt][nt][v] = 0.0f;

    auto compute_ks = [&](uint32_t aBase, uint32_t bBase, int ks) {
        const uint32_t abase = aBase + a_rt;
        const uint32_t bbase = bBase + b_rt;
        uint32_t af[4][4], bf[2][4];
        const uint32_t ac = ac0 ^ (uint32_t)((2 * ks) << 4);
        const uint32_t bc = bc0 ^ (uint32_t)((2 * ks) << 4);
        ldsm4(bf[0], bbase + bc);
        ldsm4(bf[1], bbase + 2048 + bc);
        #pragma unroll
        for (int mt = 0; mt < 4; mt++)
            ldsm4(af[mt], abase + mt * 2048 + ac);
        #pragma unroll
        for (int mt = 0; mt < 4; mt++)
            #pragma unroll
            for (int np = 0; np < 2; np++) {
                mma16816(acc[mt][2 * np],     af[mt], &bf[np][0]);
                mma16816(acc[mt][2 * np + 1], af[mt], &bf[np][2]);
            }
    };

    // one pipeline step: compute ks0..3 of C-buffer with the L-buffer loads split
    // into two 4-op bursts at ks boundaries (each covered by draining HMMAs).
    auto step = [&](uint32_t eL, uint32_t peL, uint32_t aL, uint32_t bL, uint32_t fL,
                    uint32_t fC, uint32_t pfC, uint32_t aC, uint32_t bC, uint32_t eC) {
        mbar_wait(fC, pfC);             // compute data ready (all threads' loads)
        compute_ks(aC, bC, 0);
        mbar_wait(eL, peL);             // buffer free (pre-satisfied in steady state)
        load_A(aL);
        compute_ks(aC, bC, 1);
        load_B(bL);
        cpa_arrive_noinc(fL);           // arrive when this thread's loads land
        compute_ks(aC, bC, 2);
        compute_ks(aC, bC, 3);
        if (lane == 0) mbar_arrive(eC); // warp done reading C-buffer
    };

    // prologue: 2 stages in flight (virgin buffers: no empty wait)
    load_A(aS0); load_B(bS0); cpa_arrive_noinc(F0);
    load_A(aS1); load_B(bS1); cpa_arrive_noinc(F1);

    // 30 iters: 5 rounds x 6 (parity period = lcm(3 stages, 2 phases)); all parities literal
    #pragma unroll 1
    for (int r = 0; r < 5; r++) {
        step(E2, 0, aS2, bS2, F2,  F0, 0, aS0, bS0, E0);   // u=0
        step(E0, 1, aS0, bS0, F0,  F1, 0, aS1, bS1, E1);   // u=1
        step(E1, 1, aS1, bS1, F1,  F2, 0, aS2, bS2, E2);   // u=2
        step(E2, 1, aS2, bS2, F2,  F0, 1, aS0, bS0, E0);   // u=3
        step(E0, 0, aS0, bS0, F0,  F1, 1, aS1, bS1, E1);   // u=4
        step(E1, 0, aS1, bS1, F1,  F2, 1, aS2, bS2, E2);   // u=5
    }
    // tail: iters 30,31 (no loads); full parities (it/3)&1 = 0
    mbar_wait(F0, 0);
    compute_ks(aS0, bS0, 0); compute_ks(aS0, bS0, 1);
    compute_ks(aS0, bS0, 2); compute_ks(aS0, bS0, 3);
    mbar_wait(F1, 0);
    compute_ks(aS1, bS1, 0); compute_ks(aS1, bS1, 1);
    compute_ks(aS1, bS1, 2); compute_ks(aS1, bS1, 3);

    // ---------------- epilogue: gate exchange via smem, fused LSTM ----------------
    __syncthreads();                            // all warps done before smem reuse
    float* gbuf = (float*)(smem + OFF_STAGE);   // 128 rows x 128 floats (xor-swizzled 8B slots)

    #pragma unroll
    for (int mt = 0; mt < 4; mt++) {
        #pragma unroll
        for (int nt = 0; nt < 4; nt++) {
            const int r0 = wm * 64 + mt * 16 + (lane >> 2);
            const int r1 = r0 + 8;
            const int sbase = wn * 16 + nt * 4 + (lane & 3);   // 8B slot index (64 per row)
            const uint32_t off0 = (uint32_t)r0 * 512 + (uint32_t)((sbase ^ ((r0 & 7) << 2)) << 3);
            const uint32_t off1 = (uint32_t)r1 * 512 + (uint32_t)((sbase ^ ((r1 & 7) << 2)) << 3);
            *(float2*)((char*)gbuf + off0) = make_float2(acc[mt][nt][0], acc[mt][nt][1]);
            *(float2*)((char*)gbuf + off1) = make_float2(acc[mt][nt][2], acc[mt][nt][3]);
        }
    }
    __syncthreads();

    {
        const int ocol = tid & 31;                 // output column within tile (32 outputs)
        const int rbase = tid >> 5;                // 8 row groups
        const float4 bias4 = *(const float4*)((const float*)smem + ocol * 4);
        const int obase = (n0 >> 2) + ocol;        // global output index
        #pragma unroll 4
        for (int i = 0; i < 16; i++) {
            const int r = rbase + 8 * i;
            const int b = m0 + r;
            const uint32_t off = (uint32_t)r * 512 +
                                 (uint32_t)(((2 * ocol) ^ ((r & 7) << 2)) << 3);
            float4 gt = *(const float4*)((const char*)gbuf + off);
            float gi = gt.x + bias4.x;
            float gf = gt.y + bias4.y;
            float gg = gt.z + bias4.z;
            float go = gt.w + bias4.w;
            float iv = sigf(gi), fv = sigf(gf), gv = tanhf_(gg), ov = sigf(go);
            float cold = c_in[(size_t)b * HD + obase];
            float cv = fv * cold + iv * gv;
            float hv = ov * tanhf_(cv);
            out[(size_t)b * HD + obase] = hv;
            out[(size_t)BB * HD + (size_t)b * HD + obase] = cv;
        }
    }
}

// ---------------- launch ----------------
extern "C" void kernel_launch(void* const* d_in, const int* in_sizes, int n_in,
                              void* d_out, int out_size) {
    const float* x  = (const float*)d_in[0];
    const float* h  = (const float*)d_in[1];
    const float* c  = (const float*)d_in[2];
    const float* Wx = (const float*)d_in[3];
    const float* bx = (const float*)d_in[4];
    const float* Wh = (const float*)d_in[5];
    const float* bh = (const float*)d_in[6];
    float* out = (float*)d_out;

    pack_all_kernel<<<PACK_BLOCKS, PT>>>(x, h, Wx, Wh, bx, bh);

    cudaFuncSetAttribute(lstm_gemm_kernel,
                         cudaFuncAttributeMaxDynamicSharedMemorySize, SMEM_TOTAL);
    dim3 grid(N4 / BN, BB / BM);   // (32, 64)
    lstm_gemm_kernel<<<grid, NT, SMEM_TOTAL>>>(c, out);
}